// round 4
// baseline (speedup 1.0000x reference)
#include <cuda_runtime.h>
#include <math.h>
#include <stdint.h>

#define BATCH 4
#define LSEQ  512
#define DMODEL 512
#define DFF   512
#define DINNER 256
#define MR    (BATCH*LSEQ)   /* 2048 rows */
#define MR2   (2*MR)         /* 4096 rows: merged pair */

__device__ __align__(16) float g_scratch[26u*1024u*1024u];

__device__ __forceinline__ float siluf(float x){ return x / (1.0f + expf(-x)); }
__device__ __forceinline__ float softplusf(float x){ return (x > 20.0f) ? x : log1pf(expf(x)); }

__device__ __forceinline__ uint32_t f2tf32(float x){
    uint32_t r; asm("cvt.rna.tf32.f32 %0, %1;" : "=r"(r) : "f"(x)); return r;
}
__device__ __forceinline__ void mma_tf32(float* c, const uint32_t* a, const uint32_t* b){
    asm volatile("mma.sync.aligned.m16n8k8.row.col.f32.tf32.tf32.f32 "
        "{%0,%1,%2,%3}, {%4,%5,%6,%7}, {%8,%9}, {%0,%1,%2,%3};"
        : "+f"(c[0]),"+f"(c[1]),"+f"(c[2]),"+f"(c[3])
        : "r"(a[0]),"r"(a[1]),"r"(a[2]),"r"(a[3]), "r"(b[0]),"r"(b[1]));
}

// ---------------------------------------------------------------------------
// TF32 tensor-core GEMM with deep prefetch + fused loaders/epilogues.
// C[M,N] = act((A[+A2])@W + bias) [+ P1.*P2]; ATOM: atomicAdd into pre-zeroed C.
// 128x64 tile, 256 threads (8 warps 4x2), warp tile 32x32 (2x4 m16n8k8).
// K-chunk 16, double-buffered smem, 2-chunk register prefetch.
// M%128==0, K%16==0, N arbitrary. Batched/split-K via blockIdx.z.
// flipA: A row index flipped within 512-row blocks (for up-proj).
// ---------------------------------------------------------------------------
template<int ACT, int ATOM>
__global__ __launch_bounds__(256)
void gemm_tc(const float* __restrict__ A, const float* __restrict__ A2,
             const float* __restrict__ W,
             const float* __restrict__ bias, long long biasb,
             const float* __restrict__ P1, int ldp1, long long p1b,
             const float* __restrict__ P2, int ldp2, long long p2b,
             float* __restrict__ C,
             int M, int N, int K, int lda, int ldw, int ldc,
             long long Ab, long long Wb, long long Cb, int flipA)
{
    __shared__ uint32_t As[2][128][20];
    __shared__ uint32_t Bs[2][16][72];
    const int bz = blockIdx.z;
    A += (long long)bz * Ab;  W += (long long)bz * Wb;  C += (long long)bz * Cb;
    if (A2) A2 += (long long)bz * Ab;
    if (P1) P1 += (long long)bz * p1b;
    if (P2) P2 += (long long)bz * p2b;
    const float* biasp = bias ? (bias + (long long)bz * biasb) : nullptr;
    const int t = threadIdx.x;
    const int lane = t & 31, wid = t >> 5;
    const int wm = wid >> 1, wn = wid & 1;
    const int gp = lane >> 2, tg = lane & 3;
    const int row0 = blockIdx.y * 128, col0 = blockIdx.x * 64;
    const int a_r = t >> 1, a_k = (t & 1) * 8;
    const int b_k = t >> 4, b_n = (t & 15) * 4;

    int rowA = row0 + a_r;
    if (flipA) rowA = (rowA & ~(LSEQ-1)) | ((LSEQ-1) - (rowA & (LSEQ-1)));

    float c[2][4][4] = {};
    float4 pA0[2], pA1[2], pB[2];

    const int nc = K >> 4;
    // prefetch chunks 0,1
    #pragma unroll
    for (int p = 0; p < 2; p++) {
        if (p < nc) {
            const float* ap = A + (long long)rowA * lda + p*16 + a_k;
            float4 a0 = *(const float4*)ap, a1 = *(const float4*)(ap + 4);
            if (A2) {
                const float* ap2 = A2 + (long long)rowA * lda + p*16 + a_k;
                float4 b0 = *(const float4*)ap2, b1 = *(const float4*)(ap2 + 4);
                a0.x+=b0.x; a0.y+=b0.y; a0.z+=b0.z; a0.w+=b0.w;
                a1.x+=b1.x; a1.y+=b1.y; a1.z+=b1.z; a1.w+=b1.w;
            }
            pA0[p] = a0; pA1[p] = a1;
            int gn = col0 + b_n;
            const float* wp = W + (long long)(p*16 + b_k) * ldw + gn;
            float4 bv;
            if (gn + 3 < N) bv = *(const float4*)wp;
            else {
                bv.x=(gn<N)?wp[0]:0.f; bv.y=(gn+1<N)?wp[1]:0.f;
                bv.z=(gn+2<N)?wp[2]:0.f; bv.w=(gn+3<N)?wp[3]:0.f;
            }
            pB[p] = bv;
        }
    }

    for (int i = 0; i < nc; i++) {
        const int s = i & 1;
        {
            uint32_t* as = &As[s][a_r][a_k];
            float4 a0 = pA0[s], a1 = pA1[s];
            as[0]=f2tf32(a0.x); as[1]=f2tf32(a0.y); as[2]=f2tf32(a0.z); as[3]=f2tf32(a0.w);
            as[4]=f2tf32(a1.x); as[5]=f2tf32(a1.y); as[6]=f2tf32(a1.z); as[7]=f2tf32(a1.w);
            uint32_t* bs = &Bs[s][b_k][b_n];
            float4 bv = pB[s];
            bs[0]=f2tf32(bv.x); bs[1]=f2tf32(bv.y); bs[2]=f2tf32(bv.z); bs[3]=f2tf32(bv.w);
        }
        __syncthreads();
        if (i + 2 < nc) {
            const int kb = (i + 2) * 16;
            const float* ap = A + (long long)rowA * lda + kb + a_k;
            float4 a0 = *(const float4*)ap, a1 = *(const float4*)(ap + 4);
            if (A2) {
                const float* ap2 = A2 + (long long)rowA * lda + kb + a_k;
                float4 b0 = *(const float4*)ap2, b1 = *(const float4*)(ap2 + 4);
                a0.x+=b0.x; a0.y+=b0.y; a0.z+=b0.z; a0.w+=b0.w;
                a1.x+=b1.x; a1.y+=b1.y; a1.z+=b1.z; a1.w+=b1.w;
            }
            pA0[s] = a0; pA1[s] = a1;
            int gn = col0 + b_n;
            const float* wp = W + (long long)(kb + b_k) * ldw + gn;
            float4 bv;
            if (gn + 3 < N) bv = *(const float4*)wp;
            else {
                bv.x=(gn<N)?wp[0]:0.f; bv.y=(gn+1<N)?wp[1]:0.f;
                bv.z=(gn+2<N)?wp[2]:0.f; bv.w=(gn+3<N)?wp[3]:0.f;
            }
            pB[s] = bv;
        }
        #pragma unroll
        for (int ks = 0; ks < 2; ks++) {
            const int k0 = ks * 8;
            uint32_t a[2][4], b[4][2];
            #pragma unroll
            for (int mb = 0; mb < 2; mb++) {
                int r0 = wm*32 + mb*16 + gp;
                a[mb][0] = As[s][r0  ][k0 + tg];
                a[mb][1] = As[s][r0+8][k0 + tg];
                a[mb][2] = As[s][r0  ][k0 + 4 + tg];
                a[mb][3] = As[s][r0+8][k0 + 4 + tg];
            }
            #pragma unroll
            for (int nb = 0; nb < 4; nb++) {
                int cc = wn*32 + nb*8 + gp;
                b[nb][0] = Bs[s][k0 + tg    ][cc];
                b[nb][1] = Bs[s][k0 + 4 + tg][cc];
            }
            #pragma unroll
            for (int mb = 0; mb < 2; mb++)
                #pragma unroll
                for (int nb = 0; nb < 4; nb++)
                    mma_tf32(c[mb][nb], a[mb], b[nb]);
        }
    }

    #pragma unroll
    for (int mb = 0; mb < 2; mb++) {
        #pragma unroll
        for (int half = 0; half < 2; half++) {
            long long gr = row0 + wm*32 + mb*16 + gp + half*8;
            #pragma unroll
            for (int nb = 0; nb < 4; nb++) {
                #pragma unroll
                for (int j = 0; j < 2; j++) {
                    int gn = col0 + wn*32 + nb*8 + tg*2 + j;
                    if (gn < N) {
                        float v = c[mb][nb][half*2 + j];
                        if (biasp && (!ATOM || bz == 0)) v += biasp[gn];
                        if (ACT==1) v = siluf(v);
                        if (ACT==2) v = softplusf(v);
                        if (P1) v += P1[gr*ldp1 + gn] * P2[gr*ldp2 + gn];
                        if (ATOM) atomicAdd(&C[gr*ldc + gn], v);
                        else      C[gr*ldc + gn] = v;
                    }
                }
            }
        }
    }
}

// ---------------------------------------------------------------------------
// hs0(2048x1024) -> stacked silu / flipped-silu pairs
// ---------------------------------------------------------------------------
__global__ void silu_flip_k(const float* __restrict__ hs0, float* __restrict__ sx,
                            float* __restrict__ sz, float* __restrict__ fx,
                            float* __restrict__ fz)
{
    int i = blockIdx.x*256 + threadIdx.x;
    if (i >= MR*DFF) return;
    int d = i & (DFF-1);
    int m = i >> 9;
    int b = m >> 9, tt = m & (LSEQ-1);
    float s1 = siluf(hs0[m*1024 + d]);
    float s2 = siluf(hs0[m*1024 + 512 + d]);
    sx[i] = s1; sz[i] = s2;
    int mf = (b << 9) + (LSEQ-1 - tt);
    fx[mf*DFF + d] = siluf(s1);
    fz[mf*DFF + d] = siluf(s2);
}

// ---------------------------------------------------------------------------
// Selective scan over nseq sequences of length LSEQ. Thread per (seq,d,n).
// ---------------------------------------------------------------------------
__global__ void scan_k(const float* __restrict__ delta, const float* __restrict__ u,
                       const float* __restrict__ Bm, int ldb,
                       const float* __restrict__ Alog,
                       float* __restrict__ hsum, int D, int nseq)
{
    int tid = blockIdx.x*256 + threadIdx.x;
    int n = tid & 15;
    int seg = tid >> 4;
    int d = seg % D;
    int s = seg / D;
    if (s >= nseq) return;
    float An = -expf(Alog[n]);
    float h = 0.f;
    int base = s * LSEQ;
    #pragma unroll 4
    for (int ts = 0; ts < LSEQ; ts++) {
        int r = base + ts;
        float dl = delta[r*D + d];
        float ul = u[r*D + d];
        float Bv = Bm[(long long)r*ldb + n];
        float a = expf(dl * An);
        h = fmaf(a, h, dl * ul * Bv);
        float v = h;
        v += __shfl_xor_sync(0xffffffffu, v, 1);
        v += __shfl_xor_sync(0xffffffffu, v, 2);
        v += __shfl_xor_sync(0xffffffffu, v, 4);
        v += __shfl_xor_sync(0xffffffffu, v, 8);
        if (n == 0) hsum[r*D + d] = v;
    }
}

// ---------------------------------------------------------------------------
// Fused skinny projections: q = softplus(u@qw+qb), k = softplus(Cm@kw+kb)
// One thread per (row, col16). grid = M2/16 blocks of 256.
// ---------------------------------------------------------------------------
__global__ void qk_k(const float* __restrict__ u, int D,
                     const float* __restrict__ qw, const float* __restrict__ qb,
                     const float* __restrict__ dbcd, int Np,
                     const float* __restrict__ kw, const float* __restrict__ kb,
                     float* __restrict__ qbuf, float* __restrict__ kbuf)
{
    int t = threadIdx.x;
    int c = t & 15, r16 = t >> 4;
    long long row = (long long)blockIdx.x * 16 + r16;
    const float* ar = u + row * D;
    float acc = 0.f;
    #pragma unroll 4
    for (int k = 0; k < D; k += 4) {
        float4 a4 = *(const float4*)(ar + k);
        acc = fmaf(a4.x, qw[(k+0)*16 + c], acc);
        acc = fmaf(a4.y, qw[(k+1)*16 + c], acc);
        acc = fmaf(a4.z, qw[(k+2)*16 + c], acc);
        acc = fmaf(a4.w, qw[(k+3)*16 + c], acc);
    }
    qbuf[row*16 + c] = softplusf(acc + qb[c]);
    const float* cr = dbcd + row * Np + 48;
    float acck = 0.f;
    #pragma unroll
    for (int k = 0; k < 16; k++) acck = fmaf(cr[k], kw[k*16 + c], acck);
    kbuf[row*16 + c] = softplusf(acck + kb[c]);
}

// ---------------------------------------------------------------------------
// attn[s,i,j] = softmax_j( dot(q[s,i,:], k[s,j,:]) / 16 ).  Block per (i,s).
// ---------------------------------------------------------------------------
__global__ void attn_k(const float* __restrict__ q, const float* __restrict__ k,
                       float* __restrict__ attn)
{
    const int i = blockIdx.x, s = blockIdx.y;
    __shared__ float qs[16];
    __shared__ float red[16];
    const int t = threadIdx.x;  // 256
    if (t < 16) qs[t] = q[(s*LSEQ + i)*16 + t];
    __syncthreads();
    float v[2];
    #pragma unroll
    for (int jj = 0; jj < 2; jj++) {
        int j = t + jj*256;
        const float4* kr = (const float4*)(k + (long long)(s*LSEQ + j)*16);
        float4 k0 = kr[0], k1 = kr[1], k2 = kr[2], k3 = kr[3];
        float sc = qs[0]*k0.x + qs[1]*k0.y + qs[2]*k0.z + qs[3]*k0.w
                 + qs[4]*k1.x + qs[5]*k1.y + qs[6]*k1.z + qs[7]*k1.w
                 + qs[8]*k2.x + qs[9]*k2.y + qs[10]*k2.z + qs[11]*k2.w
                 + qs[12]*k3.x + qs[13]*k3.y + qs[14]*k3.z + qs[15]*k3.w;
        v[jj] = sc * (1.0f/16.0f);
    }
    float m = fmaxf(v[0], v[1]);
    for (int o=16;o;o>>=1) m = fmaxf(m, __shfl_xor_sync(0xffffffffu, m, o));
    if ((t&31)==0) red[t>>5] = m;
    __syncthreads();
    if (t == 0) { float mm = red[0]; for (int w=1;w<8;w++) mm = fmaxf(mm, red[w]); red[0] = mm; }
    __syncthreads();
    float bm = red[0];
    v[0] = expf(v[0]-bm); v[1] = expf(v[1]-bm);
    float sm = v[0] + v[1];
    for (int o=16;o;o>>=1) sm += __shfl_xor_sync(0xffffffffu, sm, o);
    if ((t&31)==0) red[8 + (t>>5)] = sm;
    __syncthreads();
    if (t == 0) { float ss = 0.f; for (int w=0;w<8;w++) ss += red[8+w]; red[8] = ss; }
    __syncthreads();
    float inv = 1.0f / red[8];
    float* arow = attn + ((long long)s*LSEQ + i)*LSEQ;
    arow[t]     = v[0]*inv;
    arow[t+256] = v[1]*inv;
}

// ---------------------------------------------------------------------------
// Host side
// ---------------------------------------------------------------------------
struct GArgs {
    const float *A, *A2, *W, *bias; long long biasb;
    const float *P1; int ldp1; long long p1b;
    const float *P2; int ldp2; long long p2b;
    float* C; int M, N, K, lda, ldw, ldc;
    int bat; long long Ab, Wb, Cb; int flipA;
};

static inline void gemm(int act, int atom, const GArgs& g)
{
    dim3 gr((g.N + 63) / 64, g.M / 128, g.bat), bl(256);
    if (atom) {
        gemm_tc<0,1><<<gr, bl>>>(g.A, g.A2, g.W, g.bias, g.biasb, g.P1, g.ldp1, g.p1b,
            g.P2, g.ldp2, g.p2b, g.C, g.M, g.N, g.K, g.lda, g.ldw, g.ldc,
            g.Ab, g.Wb, g.Cb, g.flipA);
    } else if (act == 0) {
        gemm_tc<0,0><<<gr, bl>>>(g.A, g.A2, g.W, g.bias, g.biasb, g.P1, g.ldp1, g.p1b,
            g.P2, g.ldp2, g.p2b, g.C, g.M, g.N, g.K, g.lda, g.ldw, g.ldc,
            g.Ab, g.Wb, g.Cb, g.flipA);
    } else if (act == 1) {
        gemm_tc<1,0><<<gr, bl>>>(g.A, g.A2, g.W, g.bias, g.biasb, g.P1, g.ldp1, g.p1b,
            g.P2, g.ldp2, g.p2b, g.C, g.M, g.N, g.K, g.lda, g.ldw, g.ldc,
            g.Ab, g.Wb, g.Cb, g.flipA);
    } else {
        gemm_tc<2,0><<<gr, bl>>>(g.A, g.A2, g.W, g.bias, g.biasb, g.P1, g.ldp1, g.p1b,
            g.P2, g.ldp2, g.p2b, g.C, g.M, g.N, g.K, g.lda, g.ldw, g.ldc,
            g.Ab, g.Wb, g.Cb, g.flipA);
    }
}

static inline GArgs GA(const float* A, const float* W, const float* bias, float* C,
                       int M, int N, int K, int lda, int ldw, int ldc)
{
    GArgs g{}; g.A=A; g.A2=nullptr; g.W=W; g.bias=bias; g.biasb=0;
    g.P1=nullptr; g.ldp1=0; g.p1b=0; g.P2=nullptr; g.ldp2=0; g.p2b=0;
    g.C=C; g.M=M; g.N=N; g.K=K; g.lda=lda; g.ldw=ldw; g.ldc=ldc;
    g.bat=1; g.Ab=0; g.Wb=0; g.Cb=0; g.flipA=0;
    return g;
}

// Merged-pair SSM on u [4096 x D]
static void ssm_run2(const float* u, int D, const float* projw, int Np,
                     const float* dtw, const float* dtb, const float* Alog,
                     const float* qw, const float* qb, const float* kw, const float* kb,
                     bool useD, float* yout,
                     float* dbcd, float* delta, float* hsum, float* qbuf, float* kbuf,
                     float* attn)
{
    gemm(0, 0, GA(u, projw, nullptr, dbcd, MR2, Np, D, D, Np, Np));
    gemm(2, 0, GA(dbcd, dtw, dtb, delta, MR2, D, 32, Np, D, D));      // softplus
    scan_k<<<(8*D*16)/256, 256>>>(delta, u, dbcd + 32, Np, Alog, hsum, D, 8);
    qk_k<<<MR2/16, 256>>>(u, D, qw, qb, dbcd, Np, kw, kb, qbuf, kbuf);
    attn_k<<<dim3(LSEQ, 8), 256>>>(qbuf, kbuf, attn);
    GArgs g = GA(attn, hsum, nullptr, yout, LSEQ, D, LSEQ, LSEQ, D, D);
    g.bat = 8; g.Ab = (long long)LSEQ*LSEQ; g.Wb = (long long)LSEQ*D; g.Cb = (long long)LSEQ*D;
    if (useD) {
        g.P1 = dbcd + 64; g.ldp1 = Np; g.p1b = (long long)LSEQ*Np;
        g.P2 = u;        g.ldp2 = D;  g.p2b = (long long)LSEQ*D;
    }
    gemm(0, 0, g);
}

extern "C" void kernel_launch(void* const* d_in, const int* in_sizes, int n_in,
                              void* d_out, int out_size)
{
    (void)in_sizes; (void)n_in; (void)out_size;
    float* S = nullptr;
    cudaGetSymbolAddress((void**)&S, g_scratch);

    float* hs0   = S;                 // 2048*1024
    float* usx   = hs0   + 2097152;   // [4096 x 512]
    float* ufb   = usx   + 2097152;   // [4096 x 512]
    float* ub    = ufb   + 2097152;   // [4096 x 256]
    float* dbcd  = ub    + 1048576;   // 4096*576
    float* delta = dbcd  + 2359296;   // 4096*512
    float* hsum  = delta + 2097152;   // 4096*512
    float* qbuf  = hsum  + 2097152;   // 4096*16
    float* kbuf  = qbuf  + 65536;
    float* attn  = kbuf  + 65536;     // 8*512*512
    float* yfwd  = attn  + 2097152;   // [4096 x 512]
    float* ybwd  = yfwd  + 2097152;   // [4096 x 256]
    float* cat2  = ybwd  + 1048576;   // 2048*1024
    float* oe    = cat2  + 2097152;   // 2048*256
    float* xbuf  = oe    + 524288;    // 2048*512

    const float* x             = (const float*)d_in[0];
    const float* in_w          = (const float*)d_in[1];
    const float* in_b          = (const float*)d_in[2];
    const float* x_proj_w      = (const float*)d_in[3];
    const float* dt_w          = (const float*)d_in[4];
    const float* dt_b          = (const float*)d_in[5];
    const float* A_log         = (const float*)d_in[6];
    const float* exit_x_w      = (const float*)d_in[7];
    const float* exit_x_b      = (const float*)d_in[8];
    const float* exit_z_w      = (const float*)d_in[9];
    const float* exit_z_b      = (const float*)d_in[10];
    const float* x_proj_exit_w = (const float*)d_in[11];
    const float* dt_exit_w     = (const float*)d_in[12];
    const float* dt_exit_b     = (const float*)d_in[13];
    const float* A_log_exit    = (const float*)d_in[14];
    const float* out_inner_w   = (const float*)d_in[15];
    const float* out_inner_b   = (const float*)d_in[16];
    const float* out_exit_w    = (const float*)d_in[17];
    const float* out_exit_b    = (const float*)d_in[18];
    const float* up_w          = (const float*)d_in[19];
    const float* up_b          = (const float*)d_in[20];
    const float* out_w         = (const float*)d_in[21];
    const float* out_b         = (const float*)d_in[22];
    const float* q_in_w        = (const float*)d_in[23];
    const float* q_in_b        = (const float*)d_in[24];
    const float* k_in_w        = (const float*)d_in[25];
    const float* k_in_b        = (const float*)d_in[26];
    const float* q_ex_w        = (const float*)d_in[27];
    const float* q_ex_b        = (const float*)d_in[28];
    const float* k_ex_w        = (const float*)d_in[29];
    const float* k_ex_b        = (const float*)d_in[30];

    const float* cur = x;
    for (int l = 0; l < 2; l++) {
        const float* in_w_l = in_w + (long long)l*512*1024;
        const float* in_b_l = in_b + l*1024;
        const float* xp_l   = x_proj_w + (long long)l*512*576;
        const float* dtw_l  = dt_w + l*32*512;
        const float* dtb_l  = dt_b + l*512;
        const float* Al_l   = A_log + l*16;
        const float* exw_l  = exit_x_w + (long long)l*512*256;
        const float* exb_l  = exit_x_b + l*256;
        const float* ezw_l  = exit_z_w + (long long)l*512*256;
        const float* ezb_l  = exit_z_b + l*256;
        const float* xpe_l  = x_proj_exit_w + (long long)l*256*320;
        const float* dtew_l = dt_exit_w + l*32*256;
        const float* dteb_l = dt_exit_b + l*256;
        const float* Ale_l  = A_log_exit + l*16;
        const float* oiw_l  = out_inner_w + (long long)l*1024*512;
        const float* oib_l  = out_inner_b + l*512;
        const float* oew_l  = out_exit_w + (long long)l*512*256;
        const float* oeb_l  = out_exit_b + l*256;
        const float* upw_l  = up_w + (long long)l*256*512;
        const float* upb_l  = up_b + l*512;
        const float* ow_l   = out_w + (long long)l*1024*512;
        const float* ob_l   = out_b + l*512;
        const float* qiw_l  = q_in_w + l*512*16;
        const float* qib_l  = q_in_b + l*16;
        const float* kiw_l  = k_in_w + l*16*16;
        const float* kib_l  = k_in_b + l*16;
        const float* qew_l  = q_ex_w + l*256*16;
        const float* qeb_l  = q_ex_b + l*16;
        const float* kew_l  = k_ex_w + l*16*16;
        const float* keb_l  = k_ex_b + l*16;

        // 1. hs0 = cur @ in_w + in_b   (2048 x 1024)
        gemm(0, 0, GA(cur, in_w_l, in_b_l, hs0, MR, 1024, 512, 512, 1024, 1024));
        // 2. activations + flipped inputs
        silu_flip_k<<<(MR*DFF)/256, 256>>>(hs0, usx, usx + MR*DFF, ufb, ufb + MR*DFF);
        // 3. backward-path inputs as ONE batched launch: ub = [fx@exw+exb ; fz@ezw+ezb]
        {
            GArgs g = GA(ufb, exw_l, exb_l, ub, MR, 256, 512, 512, 256, 256);
            g.bat = 2;
            g.Ab = (long long)MR*512;
            g.Wb = (long long)(ezw_l - exw_l);
            g.biasb = (long long)(ezb_l - exb_l);
            g.Cb = (long long)MR*256;
            gemm(0, 0, g);
        }
        // 4. merged SSM pairs
        ssm_run2(usx, 512, xp_l,  576, dtw_l,  dtb_l,  Al_l,  qiw_l, qib_l, kiw_l, kib_l,
                 true,  yfwd, dbcd, delta, hsum, qbuf, kbuf, attn);
        ssm_run2(ub,  256, xpe_l, 320, dtew_l, dteb_l, Ale_l, qew_l, qeb_l, kew_l, keb_l,
                 false, ybwd, dbcd, delta, hsum, qbuf, kbuf, attn);
        // 5. pre-zero atomic targets
        cudaMemsetAsync(cat2, 0, (size_t)MR*1024*sizeof(float));
        cudaMemsetAsync(oe,   0, (size_t)MR*256*sizeof(float));
        // out_inner: single atomic split launch over the y1f/y2f concat
        {
            GArgs g = GA(yfwd, oiw_l, oib_l, cat2, MR, 512, 512, 512, 512, 1024);
            g.bat = 2; g.Ab = (long long)MR*512; g.Wb = (long long)512*512; g.Cb = 0;
            gemm(0, 1, g);
        }
        // out_exit: single atomic split launch
        {
            GArgs g = GA(ybwd, oew_l, oeb_l, oe, MR, 256, 256, 256, 256, 256);
            g.bat = 2; g.Ab = (long long)MR*256; g.Wb = (long long)256*256; g.Cb = 0;
            gemm(0, 1, g);
        }
        // up: flip fused into A loader
        {
            GArgs g = GA(oe, upw_l, upb_l, cat2 + 512, MR, 512, 256, 256, 512, 1024);
            g.flipA = 1;
            gemm(0, 0, g);
        }
        // 6. out projection with fused residual (A2 = hs0); layer 1 fuses final silu
        {
            float* dst = (l == 1) ? (float*)d_out : xbuf;
            GArgs g = GA(cat2, ow_l, ob_l, dst, MR, 512, 1024, 1024, 512, 512);
            g.A2 = hs0;
            gemm((l == 1) ? 1 : 0, 0, g);
        }
        cur = xbuf;
    }
}